// round 2
// baseline (speedup 1.0000x reference)
#include <cuda_runtime.h>
#include <math.h>

#define IN_DIM 8
#define HID 50
#define BATCH 4096
#define TLEN 512
#define ROWS 150
#define RPAD 160
#define NB 32
#define NT 320
#define GRIDN (BATCH / NB)
#define GHN_STRIDE 52

__device__ __forceinline__ float fsig(float v) {
    return 1.0f / (1.0f + __expf(-v));
}
__device__ __forceinline__ float ftanh(float v) {
    float a = fabsf(v);
    float e = __expf(-2.0f * a);
    float t = (1.0f - e) / (1.0f + e);
    return v < 0.0f ? -t : t;
}

__global__ __launch_bounds__(NT, 1) void gru_kernel(
    const float* __restrict__ x, const float* __restrict__ W_ih,
    const float* __restrict__ W_hh, const float* __restrict__ b_ih,
    const float* __restrict__ b_hh, const float* __restrict__ W_out,
    const float* __restrict__ b_out, float* __restrict__ out)
{
    extern __shared__ float sm[];
    float* Wt   = sm;                       // [HID][RPAD]  W_hh^T, padded cols
    float* Wxt  = Wt  + HID * RPAD;         // [IN_DIM][RPAD]
    float* bi   = Wxt + IN_DIM * RPAD;      // [RPAD]
    float* bh   = bi  + RPAD;               // [RPAD]
    float* hsh  = bh  + RPAD;               // [HID][NB]  hidden, transposed
    float* xsh  = hsh + HID * NB;           // [IN_DIM][NB]
    float* ssum = xsh + IN_DIM * NB;        // [NB][RPAD]  gi+gh
    float* sghn = ssum + NB * RPAD;         // [NB][GHN_STRIDE]  gh for n-gate

    const int tid = threadIdx.x;
    const int b0  = blockIdx.x * NB;
    const int tb  = tid & 7;        // batch group: 8 groups x 4 batches = 32
    const int tj  = tid >> 3;       // row group:  40 groups x 4 rows  = 160
    const int jj  = tj * 4;

    // --- load weights transposed into SMEM (one-time) ---
    for (int i = tid; i < HID * RPAD; i += NT) {
        int k = i / RPAD, j = i % RPAD;
        Wt[i] = (j < ROWS) ? W_hh[j * HID + k] : 0.0f;
    }
    for (int i = tid; i < IN_DIM * RPAD; i += NT) {
        int k = i / RPAD, j = i % RPAD;
        Wxt[i] = (j < ROWS) ? W_ih[j * IN_DIM + k] : 0.0f;
    }
    for (int j = tid; j < RPAD; j += NT) {
        bi[j] = (j < ROWS) ? b_ih[j] : 0.0f;
        bh[j] = (j < ROWS) ? b_hh[j] : 0.0f;
    }
    for (int i = tid; i < HID * NB; i += NT) hsh[i] = 0.0f;

    // prefetch x for t=0 (threads 0..255: b = tid>>3, k = tid&7)
    const float* xp = nullptr;
    float xv = 0.0f;
    if (tid < NB * IN_DIM) {
        int b = tid >> 3, k = tid & 7;
        xp = x + ((size_t)(b0 + b) * TLEN) * IN_DIM + k;
        xv = *xp;
    }
    __syncthreads();

    float bir[4], bhr[4];
    #pragma unroll
    for (int u = 0; u < 4; u++) { bir[u] = bi[jj + u]; bhr[u] = bh[jj + u]; }

    const bool is_n = (jj >= 100) && (jj < 152);   // jj in {100..148}: n-gate rows

    for (int t = 0; t < TLEN; t++) {
        // publish x_t (transposed); barrier also orders gate(t-1) h-writes
        if (tid < NB * IN_DIM) xsh[(tid & 7) * NB + (tid >> 3)] = xv;
        __syncthreads();
        if (tid < NB * IN_DIM && t + 1 < TLEN) xv = xp[(size_t)(t + 1) * IN_DIM];

        float ax[4][4], ah[4][4];
        #pragma unroll
        for (int v = 0; v < 4; v++)
            #pragma unroll
            for (int u = 0; u < 4; u++) { ax[v][u] = bir[u]; ah[v][u] = bhr[u]; }

        // gi += x @ Wxt   (K = 8)
        #pragma unroll
        for (int k = 0; k < IN_DIM; k++) {
            float4 hq = *(const float4*)&xsh[k * NB + tb * 4];
            float4 wq = *(const float4*)&Wxt[k * RPAD + jj];
            float hv[4] = {hq.x, hq.y, hq.z, hq.w};
            float wv[4] = {wq.x, wq.y, wq.z, wq.w};
            #pragma unroll
            for (int v = 0; v < 4; v++)
                #pragma unroll
                for (int u = 0; u < 4; u++) ax[v][u] += hv[v] * wv[u];
        }
        // gh += h @ Wt    (K = 50)
        #pragma unroll 10
        for (int k = 0; k < HID; k++) {
            float4 hq = *(const float4*)&hsh[k * NB + tb * 4];
            float4 wq = *(const float4*)&Wt[k * RPAD + jj];
            float hv[4] = {hq.x, hq.y, hq.z, hq.w};
            float wv[4] = {wq.x, wq.y, wq.z, wq.w};
            #pragma unroll
            for (int v = 0; v < 4; v++)
                #pragma unroll
                for (int u = 0; u < 4; u++) ah[v][u] += hv[v] * wv[u];
        }
        // stage: sum = gi+gh everywhere; gh alone for n rows
        #pragma unroll
        for (int v = 0; v < 4; v++) {
            int b = tb * 4 + v;
            float4 s = make_float4(ax[v][0] + ah[v][0], ax[v][1] + ah[v][1],
                                   ax[v][2] + ah[v][2], ax[v][3] + ah[v][3]);
            *(float4*)&ssum[b * RPAD + jj] = s;
            if (is_n) {
                float4 g = make_float4(ah[v][0], ah[v][1], ah[v][2], ah[v][3]);
                *(float4*)&sghn[b * GHN_STRIDE + (jj - 100)] = g;
            }
        }
        __syncthreads();

        // gates + hidden update: 32*50 = 1600 (b,c) pairs, 5 per thread
        #pragma unroll
        for (int i = 0; i < (NB * HID) / NT; i++) {
            int idx = tid + NT * i;
            int b = idx / HID;
            int c = idx - b * HID;
            float sr = ssum[b * RPAD + c];
            float sz = ssum[b * RPAD + c + 50];
            float sn = ssum[b * RPAD + c + 100];
            float gn = sghn[b * GHN_STRIDE + c];
            float r = fsig(sr);
            float z = fsig(sz);
            float n = ftanh(sn + (r - 1.0f) * gn);   // gi_n + r*gh_n = sn + (r-1)*gh_n
            float h = hsh[c * NB + b];
            hsh[c * NB + b] = (1.0f - z) * n + z * h;
        }
        // no trailing barrier needed: next iteration's post-xsh barrier orders
        // gate(t) h-writes before GEMM(t+1) h-reads.
    }
    __syncthreads();

    // linear head on final hidden state
    if (tid < NB) {
        float acc = b_out[0];
        #pragma unroll
        for (int c = 0; c < HID; c++) acc += hsh[c * NB + tid] * W_out[c];
        out[b0 + tid] = acc;
    }
}

extern "C" void kernel_launch(void* const* d_in, const int* in_sizes, int n_in,
                              void* d_out, int out_size) {
    const float* x     = (const float*)d_in[0];
    const float* W_ih  = (const float*)d_in[1];
    const float* W_hh  = (const float*)d_in[2];
    const float* b_ih  = (const float*)d_in[3];
    const float* b_hh  = (const float*)d_in[4];
    const float* W_out = (const float*)d_in[5];
    const float* b_out = (const float*)d_in[6];
    float* out = (float*)d_out;

    size_t smem = (size_t)(HID * RPAD + IN_DIM * RPAD + 2 * RPAD +
                           HID * NB + IN_DIM * NB + NB * RPAD +
                           NB * GHN_STRIDE) * sizeof(float);
    cudaFuncSetAttribute(gru_kernel,
                         cudaFuncAttributeMaxDynamicSharedMemorySize, (int)smem);
    gru_kernel<<<GRIDN, NT, smem>>>(x, W_ih, W_hh, b_ih, b_hh, W_out, b_out, out);
}

// round 3
// speedup vs baseline: 1.7619x; 1.7619x over previous
#include <cuda_runtime.h>
#include <math.h>

#define IN_DIM 8
#define HID 50
#define BATCH 4096
#define TLEN 512
#define ROWS 150
#define RPAD 160
#define NB 32
#define NT 320
#define GRIDN (BATCH / NB)

typedef unsigned long long ull;

// ---- packed f32x2 helpers (sm_10x) ----
__device__ __forceinline__ ull pk2(float a) {
    ull r; asm("mov.b64 %0, {%1, %1};" : "=l"(r) : "f"(a)); return r;
}
__device__ __forceinline__ ull ff2(ull a, ull b, ull c) {
    ull d; asm("fma.rn.f32x2 %0, %1, %2, %3;" : "=l"(d) : "l"(a), "l"(b), "l"(c));
    return d;
}
__device__ __forceinline__ float2 up2(ull v) {
    float2 r; asm("mov.b64 {%0, %1}, %2;" : "=f"(r.x), "=f"(r.y) : "l"(v)); return r;
}

__device__ __forceinline__ float frcp(float v) {
    float r; asm("rcp.approx.f32 %0, %1;" : "=f"(r) : "f"(v)); return r;
}
__device__ __forceinline__ float fsig(float v) {
    float e = __expf(-v);
    return frcp(1.0f + e);
}
__device__ __forceinline__ float ftanh(float v) {
    float a = fabsf(v);
    float e = __expf(-2.0f * a);
    float t = (1.0f - e) * frcp(1.0f + e);
    return v < 0.0f ? -t : t;
}

__global__ __launch_bounds__(NT, 1) void gru_kernel(
    const float* __restrict__ x, const float* __restrict__ W_ih,
    const float* __restrict__ W_hh, const float* __restrict__ b_ih,
    const float* __restrict__ b_hh, const float* __restrict__ W_out,
    const float* __restrict__ b_out, float* __restrict__ out)
{
    extern __shared__ float sm[];
    float* Wt    = sm;                        // [HID][RPAD]   W_hh^T
    float* Wxt   = Wt   + HID * RPAD;         // [IN_DIM][RPAD] W_ih^T
    float* bi    = Wxt  + IN_DIM * RPAD;      // [RPAD]  b_ih
    float* bsum  = bi   + RPAD;               // [RPAD]  b_ih + b_hh
    float* hsh   = bsum + RPAD;               // [HID][NB]  hidden (row-major rows=c)
    float* xsh   = hsh  + HID * NB;           // [2][IN_DIM][NB]  double-buffered x_t
    float* ssum0 = xsh  + 2 * IN_DIM * NB;    // [RPAD][NB]  K-half-0 partial
    float* ssum1 = ssum0 + RPAD * NB;         // [RPAD][NB]  K-half-1 partial (+biases)

    const int tid = threadIdx.x;
    const int b0  = blockIdx.x * NB;
    const int half = (tid >= 160) ? 1 : 0;    // K-split: warps 0-4 / 5-9
    const int tg  = tid - half * 160;         // 0..159 within half
    const int tb4 = (tg & 7) * 4;             // 8 batch groups x 4 batches
    const int jj  = (tg >> 3) * 8;            // 20 row groups x 8 rows

    // ---- one-time loads ----
    for (int i = tid; i < HID * RPAD; i += NT) {
        int k = i / RPAD, j = i % RPAD;
        Wt[i] = (j < ROWS) ? W_hh[j * HID + k] : 0.0f;
    }
    for (int i = tid; i < IN_DIM * RPAD; i += NT) {
        int k = i / RPAD, j = i % RPAD;
        Wxt[i] = (j < ROWS) ? W_ih[j * IN_DIM + k] : 0.0f;
    }
    for (int j = tid; j < RPAD; j += NT) {
        float vbi = (j < ROWS) ? b_ih[j] : 0.0f;
        float vbh = (j < ROWS) ? b_hh[j] : 0.0f;
        bi[j] = vbi; bsum[j] = vbi + vbh;
    }
    for (int i = tid; i < HID * NB; i += NT) hsh[i] = 0.0f;

    // prefetch x for t=0 (threads 0..255: b = tid>>3, k = tid&7)
    const float* xp = nullptr;
    float xv = 0.0f;
    if (tid < NB * IN_DIM) {
        int b = tid >> 3, k = tid & 7;
        xp = x + ((size_t)(b0 + b) * TLEN) * IN_DIM + k;
        xv = *xp;
    }
    __syncthreads();

    // bias pairs for half1 accumulator init
    ull bs[4];
    #pragma unroll
    for (int p = 0; p < 4; p++) bs[p] = *(const ull*)&bsum[jj + 2 * p];

    float* Sme = half ? ssum1 : ssum0;

    for (int t = 0; t < TLEN; t++) {
        float* xbuf = xsh + (t & 1) * (IN_DIM * NB);
        // publish x_t into parity buffer; barrier orders gate(t-1) h/x hazards
        if (tid < NB * IN_DIM) xbuf[(tid & 7) * NB + (tid >> 3)] = xv;
        __syncthreads();
        if (tid < NB * IN_DIM && t + 1 < TLEN) xv = xp[(size_t)(t + 1) * IN_DIM];

        ull acc[4][4];
        #pragma unroll
        for (int v = 0; v < 4; v++)
            #pragma unroll
            for (int p = 0; p < 4; p++) acc[v][p] = half ? bs[p] : 0ULL;

        if (!half) {
            // K-half 0: h-k = 0..28
            #pragma unroll
            for (int k = 0; k < 29; k++) {
                ulonglong2 w0 = *(const ulonglong2*)&Wt[k * RPAD + jj];
                ulonglong2 w1 = *(const ulonglong2*)&Wt[k * RPAD + jj + 4];
                float4 hq = *(const float4*)&hsh[k * NB + tb4];
                ull hp[4] = {pk2(hq.x), pk2(hq.y), pk2(hq.z), pk2(hq.w)};
                #pragma unroll
                for (int v = 0; v < 4; v++) {
                    acc[v][0] = ff2(hp[v], w0.x, acc[v][0]);
                    acc[v][1] = ff2(hp[v], w0.y, acc[v][1]);
                    acc[v][2] = ff2(hp[v], w1.x, acc[v][2]);
                    acc[v][3] = ff2(hp[v], w1.y, acc[v][3]);
                }
            }
        } else {
            // K-half 1: h-k = 29..49, then x-k = 0..7
            #pragma unroll
            for (int k = 29; k < 50; k++) {
                ulonglong2 w0 = *(const ulonglong2*)&Wt[k * RPAD + jj];
                ulonglong2 w1 = *(const ulonglong2*)&Wt[k * RPAD + jj + 4];
                float4 hq = *(const float4*)&hsh[k * NB + tb4];
                ull hp[4] = {pk2(hq.x), pk2(hq.y), pk2(hq.z), pk2(hq.w)};
                #pragma unroll
                for (int v = 0; v < 4; v++) {
                    acc[v][0] = ff2(hp[v], w0.x, acc[v][0]);
                    acc[v][1] = ff2(hp[v], w0.y, acc[v][1]);
                    acc[v][2] = ff2(hp[v], w1.x, acc[v][2]);
                    acc[v][3] = ff2(hp[v], w1.y, acc[v][3]);
                }
            }
            #pragma unroll
            for (int k = 0; k < IN_DIM; k++) {
                ulonglong2 w0 = *(const ulonglong2*)&Wxt[k * RPAD + jj];
                ulonglong2 w1 = *(const ulonglong2*)&Wxt[k * RPAD + jj + 4];
                float4 hq = *(const float4*)&xbuf[k * NB + tb4];
                ull hp[4] = {pk2(hq.x), pk2(hq.y), pk2(hq.z), pk2(hq.w)};
                #pragma unroll
                for (int v = 0; v < 4; v++) {
                    acc[v][0] = ff2(hp[v], w0.x, acc[v][0]);
                    acc[v][1] = ff2(hp[v], w0.y, acc[v][1]);
                    acc[v][2] = ff2(hp[v], w1.x, acc[v][2]);
                    acc[v][3] = ff2(hp[v], w1.y, acc[v][3]);
                }
            }
        }

        // stage partial sums, transposed [row][batch] (conflict-free STS.128)
        #pragma unroll
        for (int p = 0; p < 4; p++) {
            float2 a0 = up2(acc[0][p]), a1 = up2(acc[1][p]);
            float2 a2 = up2(acc[2][p]), a3 = up2(acc[3][p]);
            *(float4*)&Sme[(jj + 2 * p)     * NB + tb4] = make_float4(a0.x, a1.x, a2.x, a3.x);
            *(float4*)&Sme[(jj + 2 * p + 1) * NB + tb4] = make_float4(a0.y, a1.y, a2.y, a3.y);
        }
        __syncthreads();

        // gates: lanes cover consecutive batches for a fixed gate index ->
        // every LDS/STS below is conflict-free
        #pragma unroll
        for (int i = 0; i < (NB * HID) / NT; i++) {
            int idx = tid + NT * i;
            int c = idx >> 5;          // 0..49
            int b = idx & 31;
            float sr = ssum0[c * NB + b]          + ssum1[c * NB + b];
            float sz = ssum0[(c + 50) * NB + b]   + ssum1[(c + 50) * NB + b];
            float sn = ssum0[(c + 100) * NB + b]  + ssum1[(c + 100) * NB + b];
            // recompute gi_n (cheap, K=8; Wxt read is a warp-broadcast)
            float gi = bi[100 + c];
            #pragma unroll
            for (int k = 0; k < IN_DIM; k++)
                gi += xbuf[k * NB + b] * Wxt[k * RPAD + 100 + c];
            float gh = sn - gi;                     // gh_n (incl. b_hh_n)
            float r = fsig(sr);
            float z = fsig(sz);
            float n = ftanh(sn + (r - 1.0f) * gh);  // gi_n + r*gh_n
            float h = hsh[c * NB + b];
            hsh[c * NB + b] = n + z * (h - n);
        }
        // next loop-top barrier orders gate(t) writes before GEMM(t+1) reads
    }
    __syncthreads();

    // linear head on final hidden state
    if (tid < NB) {
        float acc = b_out[0];
        #pragma unroll
        for (int c = 0; c < HID; c++) acc += hsh[c * NB + tid] * W_out[c];
        out[b0 + tid] = acc;
    }
}

extern "C" void kernel_launch(void* const* d_in, const int* in_sizes, int n_in,
                              void* d_out, int out_size) {
    const float* x     = (const float*)d_in[0];
    const float* W_ih  = (const float*)d_in[1];
    const float* W_hh  = (const float*)d_in[2];
    const float* b_ih  = (const float*)d_in[3];
    const float* b_hh  = (const float*)d_in[4];
    const float* W_out = (const float*)d_in[5];
    const float* b_out = (const float*)d_in[6];
    float* out = (float*)d_out;

    size_t smem = (size_t)(HID * RPAD + IN_DIM * RPAD + 2 * RPAD +
                           HID * NB + 2 * IN_DIM * NB + 2 * RPAD * NB) * sizeof(float);
    cudaFuncSetAttribute(gru_kernel,
                         cudaFuncAttributeMaxDynamicSharedMemorySize, (int)smem);
    gru_kernel<<<GRIDN, NT, smem>>>(x, W_ih, W_hh, b_ih, b_hh, W_out, b_out, out);
}

// round 4
// speedup vs baseline: 1.8356x; 1.0419x over previous
#include <cuda_runtime.h>
#include <math.h>

#define IN_DIM 8
#define HID 50
#define BATCH 4096
#define TLEN 512
#define ROWS 150
#define RPAD 160
#define NB 32
#define NT 320
#define GRIDN (BATCH / NB)

typedef unsigned long long ull;

// ---- packed f32x2 helpers (sm_10x) ----
__device__ __forceinline__ ull pk2(float a) {
    ull r; asm("mov.b64 %0, {%1, %1};" : "=l"(r) : "f"(a)); return r;
}
__device__ __forceinline__ ull ff2(ull a, ull b, ull c) {
    ull d; asm("fma.rn.f32x2 %0, %1, %2, %3;" : "=l"(d) : "l"(a), "l"(b), "l"(c));
    return d;
}
__device__ __forceinline__ float2 up2(ull v) {
    float2 r; asm("mov.b64 {%0, %1}, %2;" : "=f"(r.x), "=f"(r.y) : "l"(v)); return r;
}

__device__ __forceinline__ float frcp(float v) {
    float r; asm("rcp.approx.f32 %0, %1;" : "=f"(r) : "f"(v)); return r;
}
__device__ __forceinline__ float fsig(float v) {
    float e = __expf(-v);
    return frcp(1.0f + e);
}
__device__ __forceinline__ float ftanh(float v) {
    float a = fabsf(v);
    float e = __expf(-2.0f * a);
    float t = (1.0f - e) * frcp(1.0f + e);
    return v < 0.0f ? -t : t;
}

__global__ __launch_bounds__(NT, 1) void gru_kernel(
    const float* __restrict__ x, const float* __restrict__ W_ih,
    const float* __restrict__ W_hh, const float* __restrict__ b_ih,
    const float* __restrict__ b_hh, const float* __restrict__ W_out,
    const float* __restrict__ b_out, float* __restrict__ out)
{
    extern __shared__ float sm[];
    float* Wt    = sm;                        // [HID][RPAD]    W_hh^T
    float* Wxt   = Wt   + HID * RPAD;         // [IN_DIM][RPAD] W_ih^T
    float* bi    = Wxt  + IN_DIM * RPAD;      // [RPAD]  b_ih
    float* bh    = bi   + RPAD;               // [RPAD]  b_hh
    float* hsh   = bh   + RPAD;               // [HID][NB]   hidden, [c][b]
    float* xsh   = hsh  + HID * NB;           // [IN_DIM][NB]  x_t transposed
    float* ssum0 = xsh  + IN_DIM * NB;        // [RPAD][NB]  K-half-0 partial (+b_hh)
    float* ssum1 = ssum0 + RPAD * NB;         // [RPAD][NB]  K-half-1 partial (+b_ih, +x)
    float* sgin  = ssum1 + RPAD * NB;         // [RPAD][NB]  gi = b_ih + x@Wx (snapshot)

    const int tid = threadIdx.x;
    const int b0  = blockIdx.x * NB;
    const int half = (tid >= 160) ? 1 : 0;    // K-split: warps 0-4 / 5-9
    const int tg  = tid - half * 160;         // 0..159 within half
    const int tb4 = (tg & 7) * 4;             // 8 batch groups x 4 batches
    const int jj  = (tg >> 3) * 8;            // 20 row groups x 8 rows

    // ---- one-time loads ----
    for (int i = tid; i < HID * RPAD; i += NT) {
        int k = i / RPAD, j = i % RPAD;
        Wt[i] = (j < ROWS) ? W_hh[j * HID + k] : 0.0f;
    }
    for (int i = tid; i < IN_DIM * RPAD; i += NT) {
        int k = i / RPAD, j = i % RPAD;
        Wxt[i] = (j < ROWS) ? W_ih[j * IN_DIM + k] : 0.0f;
    }
    for (int j = tid; j < RPAD; j += NT) {
        bi[j] = (j < ROWS) ? b_ih[j] : 0.0f;
        bh[j] = (j < ROWS) ? b_hh[j] : 0.0f;
    }
    for (int i = tid; i < HID * NB; i += NT) hsh[i] = 0.0f;

    // prefetch x for t=0 (threads 0..255: b = tid>>3, k = tid&7)
    const float* xp = nullptr;
    float xv = 0.0f;
    if (tid < NB * IN_DIM) {
        int b = tid >> 3, k = tid & 7;
        xp = x + ((size_t)(b0 + b) * TLEN) * IN_DIM + k;
        xv = *xp;
    }
    __syncthreads();

    // accumulator-init bias pairs: half0 gets b_hh, half1 gets b_ih
    const float* bini = half ? bi : bh;
    ull bs[4];
    #pragma unroll
    for (int p = 0; p < 4; p++) bs[p] = *(const ull*)&bini[jj + 2 * p];

    float* Sme = half ? ssum1 : ssum0;

    for (int t = 0; t < TLEN; t++) {
        // publish x_t (transposed); BAR A also orders gate(t-1) h-writes
        if (tid < NB * IN_DIM) xsh[(tid & 7) * NB + (tid >> 3)] = xv;
        __syncthreads();
        if (tid < NB * IN_DIM && t + 1 < TLEN) xv = xp[(size_t)(t + 1) * IN_DIM];

        ull acc[4][4];
        #pragma unroll
        for (int v = 0; v < 4; v++)
            #pragma unroll
            for (int p = 0; p < 4; p++) acc[v][p] = bs[p];

        if (!half) {
            // K-half 0: b_hh + h-k = 0..28
            #pragma unroll
            for (int k = 0; k < 29; k++) {
                ulonglong2 w0 = *(const ulonglong2*)&Wt[k * RPAD + jj];
                ulonglong2 w1 = *(const ulonglong2*)&Wt[k * RPAD + jj + 4];
                float4 hq = *(const float4*)&hsh[k * NB + tb4];
                ull hp[4] = {pk2(hq.x), pk2(hq.y), pk2(hq.z), pk2(hq.w)};
                #pragma unroll
                for (int v = 0; v < 4; v++) {
                    acc[v][0] = ff2(hp[v], w0.x, acc[v][0]);
                    acc[v][1] = ff2(hp[v], w0.y, acc[v][1]);
                    acc[v][2] = ff2(hp[v], w1.x, acc[v][2]);
                    acc[v][3] = ff2(hp[v], w1.y, acc[v][3]);
                }
            }
        } else {
            // K-half 1: b_ih + x-part first ...
            #pragma unroll
            for (int k = 0; k < IN_DIM; k++) {
                ulonglong2 w0 = *(const ulonglong2*)&Wxt[k * RPAD + jj];
                ulonglong2 w1 = *(const ulonglong2*)&Wxt[k * RPAD + jj + 4];
                float4 hq = *(const float4*)&xsh[k * NB + tb4];
                ull hp[4] = {pk2(hq.x), pk2(hq.y), pk2(hq.z), pk2(hq.w)};
                #pragma unroll
                for (int v = 0; v < 4; v++) {
                    acc[v][0] = ff2(hp[v], w0.x, acc[v][0]);
                    acc[v][1] = ff2(hp[v], w0.y, acc[v][1]);
                    acc[v][2] = ff2(hp[v], w1.x, acc[v][2]);
                    acc[v][3] = ff2(hp[v], w1.y, acc[v][3]);
                }
            }
            // ... snapshot gi = b_ih + x@Wx (needed by n-gate) ...
            #pragma unroll
            for (int p = 0; p < 4; p++) {
                float2 a0 = up2(acc[0][p]), a1 = up2(acc[1][p]);
                float2 a2 = up2(acc[2][p]), a3 = up2(acc[3][p]);
                *(float4*)&sgin[(jj + 2 * p)     * NB + tb4] = make_float4(a0.x, a1.x, a2.x, a3.x);
                *(float4*)&sgin[(jj + 2 * p + 1) * NB + tb4] = make_float4(a0.y, a1.y, a2.y, a3.y);
            }
            // ... then h-k = 29..49
            #pragma unroll
            for (int k = 29; k < 50; k++) {
                ulonglong2 w0 = *(const ulonglong2*)&Wt[k * RPAD + jj];
                ulonglong2 w1 = *(const ulonglong2*)&Wt[k * RPAD + jj + 4];
                float4 hq = *(const float4*)&hsh[k * NB + tb4];
                ull hp[4] = {pk2(hq.x), pk2(hq.y), pk2(hq.z), pk2(hq.w)};
                #pragma unroll
                for (int v = 0; v < 4; v++) {
                    acc[v][0] = ff2(hp[v], w0.x, acc[v][0]);
                    acc[v][1] = ff2(hp[v], w0.y, acc[v][1]);
                    acc[v][2] = ff2(hp[v], w1.x, acc[v][2]);
                    acc[v][3] = ff2(hp[v], w1.y, acc[v][3]);
                }
            }
        }

        // stage partial sums, transposed [row][batch] (conflict-free STS.128)
        #pragma unroll
        for (int p = 0; p < 4; p++) {
            float2 a0 = up2(acc[0][p]), a1 = up2(acc[1][p]);
            float2 a2 = up2(acc[2][p]), a3 = up2(acc[3][p]);
            *(float4*)&Sme[(jj + 2 * p)     * NB + tb4] = make_float4(a0.x, a1.x, a2.x, a3.x);
            *(float4*)&Sme[(jj + 2 * p + 1) * NB + tb4] = make_float4(a0.y, a1.y, a2.y, a3.y);
        }
        __syncthreads();   // BAR B

        // gates: per element 9 smem ops, all conflict-free
        #pragma unroll
        for (int i = 0; i < (NB * HID) / NT; i++) {
            int idx = tid + NT * i;
            int c = idx >> 5;          // 0..49 (constant per warp)
            int b = idx & 31;          // lane
            float sr = ssum0[c * NB + b]         + ssum1[c * NB + b];
            float sz = ssum0[(c + 50) * NB + b]  + ssum1[(c + 50) * NB + b];
            float sn = ssum0[(c + 100) * NB + b] + ssum1[(c + 100) * NB + b];
            float gi = sgin[(c + 100) * NB + b];    // b_ih_n + x@Wx_n
            float gh = sn - gi;                     // gh_n (incl. b_hh_n)
            float r = fsig(sr);
            float z = fsig(sz);
            float n = ftanh(sn + (r - 1.0f) * gh);  // gi_n + r*gh_n
            float h = hsh[c * NB + b];
            hsh[c * NB + b] = n + z * (h - n);
        }
        // loop-top BAR A orders gate(t) h-writes before GEMM(t+1) h-reads
    }
    __syncthreads();

    // linear head on final hidden state
    if (tid < NB) {
        float acc = b_out[0];
        #pragma unroll
        for (int c = 0; c < HID; c++) acc += hsh[c * NB + tid] * W_out[c];
        out[b0 + tid] = acc;
    }
}

extern "C" void kernel_launch(void* const* d_in, const int* in_sizes, int n_in,
                              void* d_out, int out_size) {
    const float* x     = (const float*)d_in[0];
    const float* W_ih  = (const float*)d_in[1];
    const float* W_hh  = (const float*)d_in[2];
    const float* b_ih  = (const float*)d_in[3];
    const float* b_hh  = (const float*)d_in[4];
    const float* W_out = (const float*)d_in[5];
    const float* b_out = (const float*)d_in[6];
    float* out = (float*)d_out;

    size_t smem = (size_t)(HID * RPAD + IN_DIM * RPAD + 2 * RPAD +
                           HID * NB + IN_DIM * NB + 3 * RPAD * NB) * sizeof(float);
    cudaFuncSetAttribute(gru_kernel,
                         cudaFuncAttributeMaxDynamicSharedMemorySize, (int)smem);
    gru_kernel<<<GRIDN, NT, smem>>>(x, W_ih, W_hh, b_ih, b_hh, W_out, b_out, out);
}